// round 12
// baseline (speedup 1.0000x reference)
#include <cuda_runtime.h>
#include <cuda_bf16.h>
#include <math.h>
#include <stdint.h>

#define B_   256
#define IN_  1024
#define D_   512
#define P_   2048
#define SPLITK 4
#define NT_P  (P_ / 64)     // 32 proxy n-tiles per row

// ---------------- scratch (device globals; no allocations allowed) ---------
__device__ float g_feat_part[SPLITK * B_ * D_];   // split-K partials for GEMM1
__device__ float g_featT[B_ * D_];                // tf32-rounded feat
__device__ float g_feat_n2[B_];                   // per-row ||feat||^2 (rounded feat)
__device__ float g_pmax[B_ * NT_P];               // per (row, n-tile) partial max
__device__ float g_psum[B_ * NT_P];               // per (row, n-tile) partial sumexp
__device__ float g_sy[B_];                        // s[b, y[b]]
__device__ int   g_grp[32];                       // per-(m0,n0) split-K counters
__device__ int   g_done;                          // proxy-CTA completion counter

// ==================== tf32 mma.sync helpers ================================
__device__ __forceinline__ void mma_tf32(float c[4], const uint32_t a[4], const uint32_t b[2]) {
    asm volatile("mma.sync.aligned.m16n8k8.row.col.f32.tf32.tf32.f32 "
        "{%0,%1,%2,%3}, {%4,%5,%6,%7}, {%8,%9}, {%0,%1,%2,%3};"
        : "+f"(c[0]), "+f"(c[1]), "+f"(c[2]), "+f"(c[3])
        : "r"(a[0]), "r"(a[1]), "r"(a[2]), "r"(a[3]), "r"(b[0]), "r"(b[1]));
}

__device__ __forceinline__ float to_tf32(float x) {
    uint32_t r;
    asm("cvt.rna.tf32.f32 %0, %1;" : "=r"(r) : "f"(x));
    return __uint_as_float(r);
}
__device__ __forceinline__ uint32_t fu(float x) { return __float_as_uint(x); }

// Fragment smem layout per 32-K subchunk block: row stride 44 words (176B);
// float4 at word offset t*8 + jj*4 holds {X[jj*16+t], +4+t, +8+t, +12+t} —
// one conflict-free LDS.128 per fragment fetch.
#define RS_W 44

// subchunk block sizes (+8 words pad between blocks to de-conflict stores)
#define SCW1  (128 * RS_W + 8)      // gemm1: 64 A rows + 64 B rows
#define STG1  (2 * SCW1)            // Kc=64 stage
#define BSEG1 (64 * RS_W)
#define SCW2  (192 * RS_W + 8)      // gemm23: 128 A rows + 64 B rows
#define STG2  (2 * SCW2)
#define BSEG2 (128 * RS_W)

template<int WM16, int WN8>
__device__ __forceinline__ void chunk_mma(const float* __restrict__ As,
        const float* __restrict__ Bs, int wm, int wn, int g, int t,
        float acc[WM16][WN8][4])
{
#pragma unroll
    for (int jj = 0; jj < 2; jj++) {
        float4 qa[WM16][2];
        float4 qb[WN8];
#pragma unroll
        for (int i = 0; i < WM16; i++) {
            qa[i][0] = *(const float4*)(As + (wm + i * 16 + g) * RS_W + t * 8 + jj * 4);
            qa[i][1] = *(const float4*)(As + (wm + i * 16 + 8 + g) * RS_W + t * 8 + jj * 4);
        }
#pragma unroll
        for (int nn = 0; nn < WN8; nn++)
            qb[nn] = *(const float4*)(Bs + (wn + nn * 8 + g) * RS_W + t * 8 + jj * 4);
#pragma unroll
        for (int i = 0; i < WM16; i++) {
            uint32_t a0[4] = { fu(qa[i][0].x), fu(qa[i][1].x), fu(qa[i][0].y), fu(qa[i][1].y) };
            uint32_t a1[4] = { fu(qa[i][0].z), fu(qa[i][1].z), fu(qa[i][0].w), fu(qa[i][1].w) };
#pragma unroll
            for (int nn = 0; nn < WN8; nn++) {
                uint32_t b0[2] = { fu(qb[nn].x), fu(qb[nn].y) };
                uint32_t b1[2] = { fu(qb[nn].z), fu(qb[nn].w) };
                mma_tf32(acc[i][nn], a0, b0);
                mma_tf32(acc[i][nn], a1, b1);
            }
        }
    }
}

// ---------------- GEMM1: x @ Wb^T split-K + fused last-slice combine -------
// Kc=64 phases (4 per 256-K slice); all 512 threads load 1 unit/phase.
__global__ __launch_bounds__(512, 1)
void gemm1_mma(const float* __restrict__ x, const float* __restrict__ Wb,
               const float* __restrict__ bb)
{
    extern __shared__ __align__(16) float smem[];
    int* flag = (int*)(smem + 2 * STG1);

    const int tid = threadIdx.x, wid = tid >> 5, lane = tid & 31;
    const int g = lane >> 2, t = lane & 3;
    const int n0 = blockIdx.x * 64, m0 = blockIdx.y * 64;
    const int z  = blockIdx.z;
    const int kb = z * (IN_ / SPLITK);
    const int wm = (wid & 3) * 16, wn = (wid >> 2) * 16;

    // loader mapping: r128 = row (0..63 A, 64..127 B), q -> (subchunk, jj)
    const int r128 = tid >> 2, q = tid & 3;
    const int sct = q >> 1, jjt = q & 1;
    const bool ldA = r128 < 64;
    const float* srcrow = ldA ? (x + (size_t)(m0 + r128) * IN_)
                              : (Wb + (size_t)(n0 + r128 - 64) * IN_);
    const int stoff = sct * SCW1 + (ldA ? 0 : BSEG1)
                    + (ldA ? r128 : r128 - 64) * RS_W + jjt * 4;

    float acc[1][2][4] = {};
    float4 v[4];

    auto ld = [&](int p) {
        const float4* s = (const float4*)(srcrow + kb + p * 64 + sct * 32 + jjt * 16);
        v[0] = s[0]; v[1] = s[1]; v[2] = s[2]; v[3] = s[3];
    };
    auto st = [&](int p) {
        float a0[4] = {v[0].x, v[0].y, v[0].z, v[0].w};
        float a1[4] = {v[1].x, v[1].y, v[1].z, v[1].w};
        float a2[4] = {v[2].x, v[2].y, v[2].z, v[2].w};
        float a3[4] = {v[3].x, v[3].y, v[3].z, v[3].w};
        float* dst = smem + (p & 1) * STG1 + stoff;
#pragma unroll
        for (int tt = 0; tt < 4; tt++)
            *(float4*)(dst + tt * 8) = make_float4(to_tf32(a0[tt]), to_tf32(a1[tt]),
                                                   to_tf32(a2[tt]), to_tf32(a3[tt]));
    };

    constexpr int NPH = (IN_ / SPLITK) / 64;    // 4
    ld(0); st(0); __syncthreads();
#pragma unroll 2
    for (int p = 0; p < NPH; p++) {
        if (p + 1 < NPH) ld(p + 1);
        const float* stg = smem + (p & 1) * STG1;
        chunk_mma<1, 2>(stg,        stg + BSEG1,        wm, wn, g, t, acc);
        chunk_mma<1, 2>(stg + SCW1, stg + SCW1 + BSEG1, wm, wn, g, t, acc);
        if (p + 1 < NPH) { st(p + 1); __syncthreads(); }
    }

    // write this slice's partials
    const int m = m0 + wm + g;
    {
        float* dst = g_feat_part + (size_t)z * B_ * D_;
#pragma unroll
        for (int nn = 0; nn < 2; nn++) {
            int n = n0 + wn + nn * 8 + 2 * t;
            *(float2*)(dst + (size_t)m * D_ + n)       = make_float2(acc[0][nn][0], acc[0][nn][1]);
            *(float2*)(dst + (size_t)(m + 8) * D_ + n) = make_float2(acc[0][nn][2], acc[0][nn][3]);
        }
    }

    // ---- last slice of this (m0,n0) group combines + bias + round ----------
    const int gid = blockIdx.y * 8 + blockIdx.x;
    __threadfence();
    __syncthreads();
    if (tid == 0) *flag = (atomicAdd(&g_grp[gid], 1) == SPLITK - 1) ? 1 : 0;
    __syncthreads();
    if (*flag == 0) return;
    __threadfence();                            // acquire other slices' writes

    float2 r0[2], r8[2];
#pragma unroll
    for (int nn = 0; nn < 2; nn++) {
        int n = n0 + wn + nn * 8 + 2 * t;
        float bn0 = bb[n], bn1 = bb[n + 1];
        r0[nn] = make_float2(acc[0][nn][0] + bn0, acc[0][nn][1] + bn1);
        r8[nn] = make_float2(acc[0][nn][2] + bn0, acc[0][nn][3] + bn1);
    }
    for (int zz = 0; zz < SPLITK; zz++) {
        if (zz == z) continue;
        const float* base = g_feat_part + (size_t)zz * B_ * D_;
#pragma unroll
        for (int nn = 0; nn < 2; nn++) {
            int n = n0 + wn + nn * 8 + 2 * t;
            float2 p0 = *(const float2*)(base + (size_t)m * D_ + n);
            float2 p8 = *(const float2*)(base + (size_t)(m + 8) * D_ + n);
            r0[nn].x += p0.x; r0[nn].y += p0.y;
            r8[nn].x += p8.x; r8[nn].y += p8.y;
        }
    }
#pragma unroll
    for (int nn = 0; nn < 2; nn++) {
        int n = n0 + wn + nn * 8 + 2 * t;
        *(float2*)(g_featT + (size_t)m * D_ + n) =
            make_float2(to_tf32(r0[nn].x), to_tf32(r0[nn].y));
        *(float2*)(g_featT + (size_t)(m + 8) * D_ + n) =
            make_float2(to_tf32(r8[nn].x), to_tf32(r8[nn].y));
    }
    __syncthreads();
    if (tid == 0) atomicExch(&g_grp[gid], 0);   // reset for graph replay
}

// ---------------- fused GEMM2 (out) + GEMM3 + last-CTA finalize ------------
// Tile 128(m) x 64(n), K=512 in 8 Kc=64 phases. grid (64, 2), 512 thr.
__global__ __launch_bounds__(512, 1)
void gemm23_mma(const float* __restrict__ Wm, const float* __restrict__ bm,
                const float* __restrict__ proxies, const int* __restrict__ y,
                float* __restrict__ out)
{
    extern __shared__ __align__(16) float smem[];
    float* pn2s = smem + 2 * STG2;              // [64]
    float* fn2s = pn2s + 64;                    // [128]
    float* pmx  = fn2s + 128;                   // [128][4]  (reused by finalize)
    float* psm  = pmx + 512;                    // [128][4]
    int*   flag = (int*)(psm + 512);

    const int tid = threadIdx.x, wid = tid >> 5, lane = tid & 31;
    const int g = lane >> 2, t = lane & 3;
    const int nt = blockIdx.x;                  // 0..63
    const bool isp = (nt >= 32);
    const int n0 = (nt & 31) * 64;
    const int m0 = blockIdx.y * 128;
    const float* Bmat = isp ? proxies : Wm;
    const int wm = (wid & 3) * 32, wn = (wid >> 2) * 16, wc = wid >> 2;

    // loader mapping: r = row (0..127 A, 128..191 B), h = subchunk
    const bool act = tid < 384;
    const int r = tid >> 1, h = tid & 1;
    const bool ldA = r < 128;
    const float* srcrow = ldA ? (g_featT + (size_t)(m0 + r) * D_)
                              : (Bmat + (size_t)(n0 + r - 128) * D_);
    const int stoff = h * SCW2 + (ldA ? 0 : BSEG2)
                    + (ldA ? r : r - 128) * RS_W;

    float acc[2][2][4] = {};
    float4 v[2][4];                             // 2 jj units per phase
    float sq = 0.f;                             // A: fn2; B: pn2

    auto ld = [&](int p) {
        if (act) {
#pragma unroll
            for (int jj = 0; jj < 2; jj++) {
                const float4* s = (const float4*)(srcrow + p * 64 + h * 32 + jj * 16);
                v[jj][0] = s[0]; v[jj][1] = s[1]; v[jj][2] = s[2]; v[jj][3] = s[3];
            }
        }
    };
    auto st = [&](int p) {
        if (act) {
#pragma unroll
            for (int jj = 0; jj < 2; jj++) {
                float a0[4] = {v[jj][0].x, v[jj][0].y, v[jj][0].z, v[jj][0].w};
                float a1[4] = {v[jj][1].x, v[jj][1].y, v[jj][1].z, v[jj][1].w};
                float a2[4] = {v[jj][2].x, v[jj][2].y, v[jj][2].z, v[jj][2].w};
                float a3[4] = {v[jj][3].x, v[jj][3].y, v[jj][3].z, v[jj][3].w};
#pragma unroll
                for (int u = 0; u < 4; u++)
                    sq += a0[u] * a0[u] + a1[u] * a1[u] + a2[u] * a2[u] + a3[u] * a3[u];
                float* dst = smem + (p & 1) * STG2 + stoff + jj * 4;
                if (ldA) {      // featT already tf32-rounded
#pragma unroll
                    for (int tt = 0; tt < 4; tt++)
                        *(float4*)(dst + tt * 8) = make_float4(a0[tt], a1[tt], a2[tt], a3[tt]);
                } else {        // B side: round on pack
#pragma unroll
                    for (int tt = 0; tt < 4; tt++)
                        *(float4*)(dst + tt * 8) = make_float4(to_tf32(a0[tt]), to_tf32(a1[tt]),
                                                               to_tf32(a2[tt]), to_tf32(a3[tt]));
                }
            }
        }
    };

    constexpr int NPH = D_ / 64;                // 8
    ld(0); st(0); __syncthreads();
#pragma unroll 2
    for (int p = 0; p < NPH; p++) {
        if (p + 1 < NPH) ld(p + 1);
        const float* stg = smem + (p & 1) * STG2;
        chunk_mma<2, 2>(stg,        stg + BSEG2,        wm, wn, g, t, acc);
        chunk_mma<2, 2>(stg + SCW2, stg + SCW2 + BSEG2, wm, wn, g, t, acc);
        if (p + 1 < NPH) { st(p + 1); __syncthreads(); }
    }

    // row sumsq: (r, h=0),(r, h=1) on adjacent lanes -> pair shuffle
    {
        float sb = sq + __shfl_xor_sync(0xffffffffu, sq, 1);
        if (act && (lane & 1) == 0) {
            if (ldA) fn2s[tid >> 1] = sb;
            else     pn2s[(tid - 256) >> 1] = sb;
        }
    }
    __syncthreads();

    if (!isp) {
#pragma unroll
        for (int i = 0; i < 2; i++) {
            int m = m0 + wm + i * 16 + g;
#pragma unroll
            for (int nn = 0; nn < 2; nn++) {
                int n = n0 + wn + nn * 8 + 2 * t;
                float bn0 = bm[n], bn1 = bm[n + 1];
                *(float2*)(out + (size_t)m * P_ + n) =
                    make_float2(acc[i][nn][0] + bn0, acc[i][nn][1] + bn1);
                *(float2*)(out + (size_t)(m + 8) * P_ + n) =
                    make_float2(acc[i][nn][2] + bn0, acc[i][nn][3] + bn1);
            }
        }
        return;
    }

    // export fn2 for reg_e (2 CTAs cover all 256 rows)
    if (nt == 32 && tid < 128) g_feat_n2[m0 + tid] = fn2s[tid];

    // proxy: s = 2*dot - fn2 - pn2 in regs -> per-(row, warp) (max, sumexp)
#pragma unroll
    for (int i = 0; i < 2; i++) {
        const int rA = wm + i * 16 + g;
        const int rB = rA + 8;
        const float fa = fn2s[rA], fb = fn2s[rB];
        const int ya = y[m0 + rA], yb = y[m0 + rB];
        float sA[4], sB[4];
#pragma unroll
        for (int nn = 0; nn < 2; nn++) {
            int nl = wn + nn * 8 + 2 * t;
            float p0 = pn2s[nl], p1 = pn2s[nl + 1];
            sA[nn * 2 + 0] = 2.f * acc[i][nn][0] - fa - p0;
            sA[nn * 2 + 1] = 2.f * acc[i][nn][1] - fa - p1;
            sB[nn * 2 + 0] = 2.f * acc[i][nn][2] - fb - p0;
            sB[nn * 2 + 1] = 2.f * acc[i][nn][3] - fb - p1;
            int n = n0 + nl;
            if (n     == ya) g_sy[m0 + rA] = sA[nn * 2 + 0];
            if (n + 1 == ya) g_sy[m0 + rA] = sA[nn * 2 + 1];
            if (n     == yb) g_sy[m0 + rB] = sB[nn * 2 + 0];
            if (n + 1 == yb) g_sy[m0 + rB] = sB[nn * 2 + 1];
        }
        float mA = fmaxf(fmaxf(sA[0], sA[1]), fmaxf(sA[2], sA[3]));
        float mB = fmaxf(fmaxf(sB[0], sB[1]), fmaxf(sB[2], sB[3]));
        float eA = expf(sA[0] - mA) + expf(sA[1] - mA)
                 + expf(sA[2] - mA) + expf(sA[3] - mA);
        float eB = expf(sB[0] - mB) + expf(sB[1] - mB)
                 + expf(sB[2] - mB) + expf(sB[3] - mB);
#pragma unroll
        for (int o = 1; o <= 2; o <<= 1) {
            float mA2 = __shfl_xor_sync(0xffffffffu, mA, o);
            float eA2 = __shfl_xor_sync(0xffffffffu, eA, o);
            float mB2 = __shfl_xor_sync(0xffffffffu, mB, o);
            float eB2 = __shfl_xor_sync(0xffffffffu, eB, o);
            float M = fmaxf(mA, mA2);
            eA = eA * expf(mA - M) + eA2 * expf(mA2 - M); mA = M;
            M = fmaxf(mB, mB2);
            eB = eB * expf(mB - M) + eB2 * expf(mB2 - M); mB = M;
        }
        if (t == 0) {
            pmx[rA * 4 + wc] = mA; psm[rA * 4 + wc] = eA;
            pmx[rB * 4 + wc] = mB; psm[rB * 4 + wc] = eB;
        }
    }
    __syncthreads();
    if (tid < 128) {
        float4 m4 = *(const float4*)(pmx + tid * 4);
        float4 s4 = *(const float4*)(psm + tid * 4);
        float M = fmaxf(fmaxf(m4.x, m4.y), fmaxf(m4.z, m4.w));
        float S = s4.x * expf(m4.x - M) + s4.y * expf(m4.y - M)
                + s4.z * expf(m4.z - M) + s4.w * expf(m4.w - M);
        int idx = (m0 + tid) * NT_P + (nt - 32);
        g_pmax[idx] = M;
        g_psum[idx] = S;
    }

    // ---- last-done proxy CTA finalizes loss + reg_e ------------------------
    __threadfence();
    __syncthreads();
    if (tid == 0) *flag = (atomicAdd(&g_done, 1) == 63) ? 1 : 0;
    __syncthreads();
    if (*flag == 0) return;
    __threadfence();

    float* r1 = pmx;                            // reuse smem [256]
    float* r2 = pmx + 256;
    {
        const int b = tid >> 1, q2 = tid & 1;
        const float4* pm = (const float4*)(g_pmax + b * NT_P + q2 * 16);
        const float4* ps = (const float4*)(g_psum + b * NT_P + q2 * 16);
        float4 m0v = pm[0], m1v = pm[1], m2v = pm[2], m3v = pm[3];
        float4 s0v = ps[0], s1v = ps[1], s2v = ps[2], s3v = ps[3];
        float M = fmaxf(fmaxf(fmaxf(m0v.x, m0v.y), fmaxf(m0v.z, m0v.w)),
                        fmaxf(fmaxf(m1v.x, m1v.y), fmaxf(m1v.z, m1v.w)));
        M = fmaxf(M, fmaxf(fmaxf(fmaxf(m2v.x, m2v.y), fmaxf(m2v.z, m2v.w)),
                           fmaxf(fmaxf(m3v.x, m3v.y), fmaxf(m3v.z, m3v.w))));
        float S = s0v.x * expf(m0v.x - M) + s0v.y * expf(m0v.y - M)
                + s0v.z * expf(m0v.z - M) + s0v.w * expf(m0v.w - M)
                + s1v.x * expf(m1v.x - M) + s1v.y * expf(m1v.y - M)
                + s1v.z * expf(m1v.z - M) + s1v.w * expf(m1v.w - M)
                + s2v.x * expf(m2v.x - M) + s2v.y * expf(m2v.y - M)
                + s2v.z * expf(m2v.z - M) + s2v.w * expf(m2v.w - M)
                + s3v.x * expf(m3v.x - M) + s3v.y * expf(m3v.y - M)
                + s3v.z * expf(m3v.z - M) + s3v.w * expf(m3v.w - M);
        float M2 = __shfl_xor_sync(0xffffffffu, M, 1);
        float S2 = __shfl_xor_sync(0xffffffffu, S, 1);
        float Mn = fmaxf(M, M2);
        S = S * expf(M - Mn) + S2 * expf(M2 - Mn);
        if (q2 == 0) {
            r1[b] = g_sy[b] - Mn - logf(S);     // logp[b, y[b]]
            r2[b] = sqrtf(g_feat_n2[b]);
        }
    }
    __syncthreads();
    for (int stp = 128; stp > 0; stp >>= 1) {
        if (tid < stp) { r1[tid] += r1[tid + stp]; r2[tid] += r2[tid + stp]; }
        __syncthreads();
    }
    if (tid == 0) {
        out[(size_t)B_ * P_]     = -r1[0] / (float)B_;  // loss
        out[(size_t)B_ * P_ + 1] =  r2[0] / (float)B_;  // reg_e
        g_done = 0;                              // reset for graph replay
    }
}

// ---------------- launch ----------------------------------------------------
extern "C" void kernel_launch(void* const* d_in, const int* in_sizes, int n_in,
                              void* d_out, int out_size)
{
    const float* x       = (const float*)d_in[0];
    const int*   y       = (const int*)  d_in[1];
    const float* Wb      = (const float*)d_in[2];
    const float* bb      = (const float*)d_in[3];
    const float* Wm      = (const float*)d_in[4];
    const float* bm      = (const float*)d_in[5];
    const float* proxies = (const float*)d_in[6];
    float* out = (float*)d_out;

    const int SMEM1 = (2 * STG1 + 1) * 4;                          // ~90.2 KB
    const int SMEM2 = (2 * STG2 + 64 + 128 + 512 + 512 + 1) * 4;   // ~140.2 KB
    cudaFuncSetAttribute(gemm1_mma,  cudaFuncAttributeMaxDynamicSharedMemorySize, SMEM1);
    cudaFuncSetAttribute(gemm23_mma, cudaFuncAttributeMaxDynamicSharedMemorySize, SMEM2);

    // 1) feat: split-K GEMM + fused last-slice combine (128 CTAs)
    gemm1_mma<<<dim3(D_ / 64, B_ / 64, SPLITK), 512, SMEM1>>>(x, Wb, bb);
    // 2) fused out-head + proxy softmax partials + last-CTA finalize
    gemm23_mma<<<dim3(64, B_ / 128), 512, SMEM2>>>(Wm, bm, proxies, y, out);
}

// round 13
// speedup vs baseline: 1.0963x; 1.0963x over previous
#include <cuda_runtime.h>
#include <cuda_bf16.h>
#include <math.h>
#include <stdint.h>

#define B_   256
#define IN_  1024
#define D_   512
#define P_   2048
#define SPLITK 4
#define NT_P  (P_ / 64)     // 32 proxy n-tiles per row

// ---------------- scratch (device globals; no allocations allowed) ---------
__device__ float g_feat_part[SPLITK * B_ * D_];   // split-K partials for GEMM1
__device__ float g_featT[B_ * D_];                // tf32-rounded feat
__device__ float g_feat_n2[B_];                   // per-row ||feat||^2 (rounded feat)
__device__ float g_pmax[B_ * NT_P];               // per (row, n-tile) partial max
__device__ float g_psum[B_ * NT_P];               // per (row, n-tile) partial sumexp
__device__ float g_sy[B_];                        // s[b, y[b]]
__device__ int   g_grp[32];                       // per-(m0,n0) split-K counters
__device__ int   g_done;                          // proxy-CTA completion counter

// ==================== tf32 mma.sync helpers ================================
__device__ __forceinline__ void mma_tf32(float c[4], const uint32_t a[4], const uint32_t b[2]) {
    asm volatile("mma.sync.aligned.m16n8k8.row.col.f32.tf32.tf32.f32 "
        "{%0,%1,%2,%3}, {%4,%5,%6,%7}, {%8,%9}, {%0,%1,%2,%3};"
        : "+f"(c[0]), "+f"(c[1]), "+f"(c[2]), "+f"(c[3])
        : "r"(a[0]), "r"(a[1]), "r"(a[2]), "r"(a[3]), "r"(b[0]), "r"(b[1]));
}

__device__ __forceinline__ float to_tf32(float x) {
    uint32_t r;
    asm("cvt.rna.tf32.f32 %0, %1;" : "=r"(r) : "f"(x));
    return __uint_as_float(r);
}
__device__ __forceinline__ uint32_t fu(float x) { return __float_as_uint(x); }

// SMEM layout per tile row (Kc=32 floats): float4 at word offset t*8 + jj*4
// holds the two k-pairs thread (k-lane t) needs for mma j = 2jj, 2jj+1 in one
// LDS.128. Row stride 44 words (176B): conflict-free fragment LDS.128.
#define RS_W 44

// One Kc=32 chunk of warp mma. Two k8 passes are issued SEPARATELY so no two
// consecutive mmas share an accumulator (RAW distance = WM16*WN8 >= 4).
template<int WM16, int WN8>
__device__ __forceinline__ void chunk_mma(const float* __restrict__ As,
        const float* __restrict__ Bs, int wm, int wn, int g, int t,
        float acc[WM16][WN8][4])
{
#pragma unroll
    for (int jj = 0; jj < 2; jj++) {
        float4 qa[WM16][2];
        float4 qb[WN8];
#pragma unroll
        for (int i = 0; i < WM16; i++) {
            qa[i][0] = *(const float4*)(As + (wm + i * 16 + g) * RS_W + t * 8 + jj * 4);
            qa[i][1] = *(const float4*)(As + (wm + i * 16 + 8 + g) * RS_W + t * 8 + jj * 4);
        }
#pragma unroll
        for (int nn = 0; nn < WN8; nn++)
            qb[nn] = *(const float4*)(Bs + (wn + nn * 8 + g) * RS_W + t * 8 + jj * 4);

        uint32_t a0[WM16][4], a1[WM16][4], b0[WN8][2], b1[WN8][2];
#pragma unroll
        for (int i = 0; i < WM16; i++) {
            a0[i][0] = fu(qa[i][0].x); a0[i][1] = fu(qa[i][1].x);
            a0[i][2] = fu(qa[i][0].y); a0[i][3] = fu(qa[i][1].y);
            a1[i][0] = fu(qa[i][0].z); a1[i][1] = fu(qa[i][1].z);
            a1[i][2] = fu(qa[i][0].w); a1[i][3] = fu(qa[i][1].w);
        }
#pragma unroll
        for (int nn = 0; nn < WN8; nn++) {
            b0[nn][0] = fu(qb[nn].x); b0[nn][1] = fu(qb[nn].y);
            b1[nn][0] = fu(qb[nn].z); b1[nn][1] = fu(qb[nn].w);
        }
        // k8 pass 0: all accumulators touched once (independent mmas)
#pragma unroll
        for (int i = 0; i < WM16; i++)
#pragma unroll
            for (int nn = 0; nn < WN8; nn++)
                mma_tf32(acc[i][nn], a0[i], b0[nn]);
        // k8 pass 1
#pragma unroll
        for (int i = 0; i < WM16; i++)
#pragma unroll
            for (int nn = 0; nn < WN8; nn++)
                mma_tf32(acc[i][nn], a1[i], b1[nn]);
    }
}

// ---------------- GEMM1: x @ Wb^T split-K + fused last-slice combine -------
__global__ __launch_bounds__(512, 1)
void gemm1_mma(const float* __restrict__ x, const float* __restrict__ Wb,
               const float* __restrict__ bb)
{
    extern __shared__ __align__(16) float smem[];
    constexpr int TW = 64 * RS_W;
    constexpr int STG = 2 * TW;
    int* flag = (int*)(smem + 2 * STG);

    const int tid = threadIdx.x, wid = tid >> 5, lane = tid & 31;
    const int g = lane >> 2, t = lane & 3;
    const int n0 = blockIdx.x * 64, m0 = blockIdx.y * 64;
    const int z  = blockIdx.z;
    const int kb = z * (IN_ / SPLITK);
    const int wm = (wid & 3) * 16, wn = (wid >> 2) * 16;

    const bool isA = tid < 128, act = tid < 256;
    const int task = isA ? tid : tid - 128;
    const int r = task >> 1, jj = task & 1;
    const float* src = isA ? (x + (size_t)(m0 + r) * IN_) : (Wb + (size_t)(n0 + r) * IN_);
    const int seg = isA ? 0 : TW;

    float acc[1][2][4] = {};
    float4 v[4];

    auto ld = [&](int c) {
        if (act) {
            const float4* p = (const float4*)(src + kb + c * 32 + jj * 16);
            v[0] = p[0]; v[1] = p[1]; v[2] = p[2]; v[3] = p[3];
        }
    };
    auto st = [&](int c) {
        if (act) {
            float a0[4] = {v[0].x, v[0].y, v[0].z, v[0].w};
            float a1[4] = {v[1].x, v[1].y, v[1].z, v[1].w};
            float a2[4] = {v[2].x, v[2].y, v[2].z, v[2].w};
            float a3[4] = {v[3].x, v[3].y, v[3].z, v[3].w};
            float* dst = smem + (c & 1) * STG + seg + r * RS_W + jj * 4;
#pragma unroll
            for (int tt = 0; tt < 4; tt++)
                *(float4*)(dst + tt * 8) = make_float4(to_tf32(a0[tt]), to_tf32(a1[tt]),
                                                       to_tf32(a2[tt]), to_tf32(a3[tt]));
        }
    };

    ld(0); st(0); __syncthreads();
    constexpr int NCH = (IN_ / SPLITK) / 32;    // 8
    for (int c = 0; c < NCH; c++) {
        if (c + 1 < NCH) ld(c + 1);
        const float* stg = smem + (c & 1) * STG;
        chunk_mma<1, 2>(stg, stg + TW, wm, wn, g, t, acc);
        if (c + 1 < NCH) { st(c + 1); __syncthreads(); }
    }

    // write this slice's partials
    const int m = m0 + wm + g;
    {
        float* dst = g_feat_part + (size_t)z * B_ * D_;
#pragma unroll
        for (int nn = 0; nn < 2; nn++) {
            int n = n0 + wn + nn * 8 + 2 * t;
            *(float2*)(dst + (size_t)m * D_ + n)       = make_float2(acc[0][nn][0], acc[0][nn][1]);
            *(float2*)(dst + (size_t)(m + 8) * D_ + n) = make_float2(acc[0][nn][2], acc[0][nn][3]);
        }
    }

    // ---- last slice of this (m0,n0) group combines + bias + round ----------
    const int gid = blockIdx.y * 8 + blockIdx.x;
    __threadfence();
    __syncthreads();
    if (tid == 0) *flag = (atomicAdd(&g_grp[gid], 1) == SPLITK - 1) ? 1 : 0;
    __syncthreads();
    if (*flag == 0) return;
    __threadfence();                            // acquire other slices' writes

    float2 r0[2], r8[2];
#pragma unroll
    for (int nn = 0; nn < 2; nn++) {
        int n = n0 + wn + nn * 8 + 2 * t;
        float bn0 = bb[n], bn1 = bb[n + 1];
        r0[nn] = make_float2(acc[0][nn][0] + bn0, acc[0][nn][1] + bn1);
        r8[nn] = make_float2(acc[0][nn][2] + bn0, acc[0][nn][3] + bn1);
    }
    for (int zz = 0; zz < SPLITK; zz++) {
        if (zz == z) continue;
        const float* base = g_feat_part + (size_t)zz * B_ * D_;
#pragma unroll
        for (int nn = 0; nn < 2; nn++) {
            int n = n0 + wn + nn * 8 + 2 * t;
            float2 p0 = *(const float2*)(base + (size_t)m * D_ + n);
            float2 p8 = *(const float2*)(base + (size_t)(m + 8) * D_ + n);
            r0[nn].x += p0.x; r0[nn].y += p0.y;
            r8[nn].x += p8.x; r8[nn].y += p8.y;
        }
    }
#pragma unroll
    for (int nn = 0; nn < 2; nn++) {
        int n = n0 + wn + nn * 8 + 2 * t;
        *(float2*)(g_featT + (size_t)m * D_ + n) =
            make_float2(to_tf32(r0[nn].x), to_tf32(r0[nn].y));
        *(float2*)(g_featT + (size_t)(m + 8) * D_ + n) =
            make_float2(to_tf32(r8[nn].x), to_tf32(r8[nn].y));
    }
    __syncthreads();
    if (tid == 0) atomicExch(&g_grp[gid], 0);   // reset for graph replay
}

// ---------------- fused GEMM2 (out) + GEMM3 + last-CTA finalize ------------
// Tile 128(m) x 64(n), K=512. grid (64, 2) = 128 CTAs, 512 thr.
__global__ __launch_bounds__(512, 1)
void gemm23_mma(const float* __restrict__ Wm, const float* __restrict__ bm,
                const float* __restrict__ proxies, const int* __restrict__ y,
                float* __restrict__ out)
{
    extern __shared__ __align__(16) float smem[];
    constexpr int TAW = 128 * RS_W;
    constexpr int TBW = 64 * RS_W;
    constexpr int STG = TAW + TBW;
    float* pn2s = smem + 2 * STG;               // [64]
    float* fn2s = pn2s + 64;                    // [128]
    float* pmx  = fn2s + 128;                   // [128][4]  (reused by finalize)
    float* psm  = pmx + 512;                    // [128][4]
    int*   flag = (int*)(psm + 512);

    const int tid = threadIdx.x, wid = tid >> 5, lane = tid & 31;
    const int g = lane >> 2, t = lane & 3;
    const int nt = blockIdx.x;                  // 0..63
    const bool isp = (nt >= 32);
    const int n0 = (nt & 31) * 64;
    const int m0 = blockIdx.y * 128;
    const float* Bmat = isp ? proxies : Wm;
    const int wm = (wid & 3) * 32, wn = (wid >> 2) * 16, wc = wid >> 2;

    const bool isA = tid < 256, act = tid < 384;
    const int task = isA ? tid : tid - 256;
    const int r = task >> 1, jj = task & 1;
    const float* src = isA ? (g_featT + (size_t)(m0 + r) * D_)
                           : (Bmat + (size_t)(n0 + r) * D_);
    const int seg = isA ? 0 : TAW;

    float acc[2][2][4] = {};
    float4 v[4];
    float sq = 0.f;                             // A threads: fn2; B threads: pn2

    auto ld = [&](int c) {
        if (act) {
            const float4* p = (const float4*)(src + c * 32 + jj * 16);
            v[0] = p[0]; v[1] = p[1]; v[2] = p[2]; v[3] = p[3];
        }
    };
    auto st = [&](int c) {
        if (act) {
            float a0[4] = {v[0].x, v[0].y, v[0].z, v[0].w};
            float a1[4] = {v[1].x, v[1].y, v[1].z, v[1].w};
            float a2[4] = {v[2].x, v[2].y, v[2].z, v[2].w};
            float a3[4] = {v[3].x, v[3].y, v[3].z, v[3].w};
#pragma unroll
            for (int u = 0; u < 4; u++)
                sq += a0[u] * a0[u] + a1[u] * a1[u] + a2[u] * a2[u] + a3[u] * a3[u];
            float* dst = smem + (c & 1) * STG + seg + r * RS_W + jj * 4;
            if (isA) {      // feat already tf32-rounded
#pragma unroll
                for (int tt = 0; tt < 4; tt++)
                    *(float4*)(dst + tt * 8) = make_float4(a0[tt], a1[tt], a2[tt], a3[tt]);
            } else {        // B side: round on pack
#pragma unroll
                for (int tt = 0; tt < 4; tt++)
                    *(float4*)(dst + tt * 8) = make_float4(to_tf32(a0[tt]), to_tf32(a1[tt]),
                                                           to_tf32(a2[tt]), to_tf32(a3[tt]));
            }
        }
    };

    ld(0); st(0); __syncthreads();
    constexpr int NCH = D_ / 32;                // 16
    for (int c = 0; c < NCH; c++) {
        if (c + 1 < NCH) ld(c + 1);
        const float* stg = smem + (c & 1) * STG;
        chunk_mma<2, 2>(stg, stg + TAW, wm, wn, g, t, acc);
        if (c + 1 < NCH) { st(c + 1); __syncthreads(); }
    }

    // row sumsq: tasks (r,0),(r,1) sit on adjacent lanes -> pair shuffle
    {
        float sb = sq + __shfl_xor_sync(0xffffffffu, sq, 1);
        if (act && (lane & 1) == 0) {
            if (isA) fn2s[tid >> 1] = sb;
            else     pn2s[(tid - 256) >> 1] = sb;
        }
    }
    __syncthreads();

    if (!isp) {
#pragma unroll
        for (int i = 0; i < 2; i++) {
            int m = m0 + wm + i * 16 + g;
#pragma unroll
            for (int nn = 0; nn < 2; nn++) {
                int n = n0 + wn + nn * 8 + 2 * t;
                float bn0 = bm[n], bn1 = bm[n + 1];
                *(float2*)(out + (size_t)m * P_ + n) =
                    make_float2(acc[i][nn][0] + bn0, acc[i][nn][1] + bn1);
                *(float2*)(out + (size_t)(m + 8) * P_ + n) =
                    make_float2(acc[i][nn][2] + bn0, acc[i][nn][3] + bn1);
            }
        }
        return;
    }

    // export fn2 for reg_e (2 CTAs cover all 256 rows)
    if (nt == 32 && tid < 128) g_feat_n2[m0 + tid] = fn2s[tid];

    // proxy: s = 2*dot - fn2 - pn2 in regs -> per-(row, warp) (max, sumexp)
#pragma unroll
    for (int i = 0; i < 2; i++) {
        const int rA = wm + i * 16 + g;
        const int rB = rA + 8;
        const float fa = fn2s[rA], fb = fn2s[rB];
        const int ya = y[m0 + rA], yb = y[m0 + rB];
        float sA[4], sB[4];
#pragma unroll
        for (int nn = 0; nn < 2; nn++) {
            int nl = wn + nn * 8 + 2 * t;
            float p0 = pn2s[nl], p1 = pn2s[nl + 1];
            sA[nn * 2 + 0] = 2.f * acc[i][nn][0] - fa - p0;
            sA[nn * 2 + 1] = 2.f * acc[i][nn][1] - fa - p1;
            sB[nn * 2 + 0] = 2.f * acc[i][nn][2] - fb - p0;
            sB[nn * 2 + 1] = 2.f * acc[i][nn][3] - fb - p1;
            int n = n0 + nl;
            if (n     == ya) g_sy[m0 + rA] = sA[nn * 2 + 0];
            if (n + 1 == ya) g_sy[m0 + rA] = sA[nn * 2 + 1];
            if (n     == yb) g_sy[m0 + rB] = sB[nn * 2 + 0];
            if (n + 1 == yb) g_sy[m0 + rB] = sB[nn * 2 + 1];
        }
        float mA = fmaxf(fmaxf(sA[0], sA[1]), fmaxf(sA[2], sA[3]));
        float mB = fmaxf(fmaxf(sB[0], sB[1]), fmaxf(sB[2], sB[3]));
        float eA = expf(sA[0] - mA) + expf(sA[1] - mA)
                 + expf(sA[2] - mA) + expf(sA[3] - mA);
        float eB = expf(sB[0] - mB) + expf(sB[1] - mB)
                 + expf(sB[2] - mB) + expf(sB[3] - mB);
#pragma unroll
        for (int o = 1; o <= 2; o <<= 1) {
            float mA2 = __shfl_xor_sync(0xffffffffu, mA, o);
            float eA2 = __shfl_xor_sync(0xffffffffu, eA, o);
            float mB2 = __shfl_xor_sync(0xffffffffu, mB, o);
            float eB2 = __shfl_xor_sync(0xffffffffu, eB, o);
            float M = fmaxf(mA, mA2);
            eA = eA * expf(mA - M) + eA2 * expf(mA2 - M); mA = M;
            M = fmaxf(mB, mB2);
            eB = eB * expf(mB - M) + eB2 * expf(mB2 - M); mB = M;
        }
        if (t == 0) {
            pmx[rA * 4 + wc] = mA; psm[rA * 4 + wc] = eA;
            pmx[rB * 4 + wc] = mB; psm[rB * 4 + wc] = eB;
        }
    }
    __syncthreads();
    if (tid < 128) {
        float4 m4 = *(const float4*)(pmx + tid * 4);
        float4 s4 = *(const float4*)(psm + tid * 4);
        float M = fmaxf(fmaxf(m4.x, m4.y), fmaxf(m4.z, m4.w));
        float S = s4.x * expf(m4.x - M) + s4.y * expf(m4.y - M)
                + s4.z * expf(m4.z - M) + s4.w * expf(m4.w - M);
        int idx = (m0 + tid) * NT_P + (nt - 32);
        g_pmax[idx] = M;
        g_psum[idx] = S;
    }

    // ---- last-done proxy CTA finalizes loss + reg_e ------------------------
    __threadfence();
    __syncthreads();
    if (tid == 0) *flag = (atomicAdd(&g_done, 1) == 63) ? 1 : 0;
    __syncthreads();
    if (*flag == 0) return;
    __threadfence();

    float* r1 = pmx;                            // reuse smem [256]
    float* r2 = pmx + 256;
    {
        const int b = tid >> 1, q2 = tid & 1;
        const float4* pm = (const float4*)(g_pmax + b * NT_P + q2 * 16);
        const float4* ps = (const float4*)(g_psum + b * NT_P + q2 * 16);
        float4 m0v = pm[0], m1v = pm[1], m2v = pm[2], m3v = pm[3];
        float4 s0v = ps[0], s1v = ps[1], s2v = ps[2], s3v = ps[3];
        float M = fmaxf(fmaxf(fmaxf(m0v.x, m0v.y), fmaxf(m0v.z, m0v.w)),
                        fmaxf(fmaxf(m1v.x, m1v.y), fmaxf(m1v.z, m1v.w)));
        M = fmaxf(M, fmaxf(fmaxf(fmaxf(m2v.x, m2v.y), fmaxf(m2v.z, m2v.w)),
                           fmaxf(fmaxf(m3v.x, m3v.y), fmaxf(m3v.z, m3v.w))));
        float S = s0v.x * expf(m0v.x - M) + s0v.y * expf(m0v.y - M)
                + s0v.z * expf(m0v.z - M) + s0v.w * expf(m0v.w - M)
                + s1v.x * expf(m1v.x - M) + s1v.y * expf(m1v.y - M)
                + s1v.z * expf(m1v.z - M) + s1v.w * expf(m1v.w - M)
                + s2v.x * expf(m2v.x - M) + s2v.y * expf(m2v.y - M)
                + s2v.z * expf(m2v.z - M) + s2v.w * expf(m2v.w - M)
                + s3v.x * expf(m3v.x - M) + s3v.y * expf(m3v.y - M)
                + s3v.z * expf(m3v.z - M) + s3v.w * expf(m3v.w - M);
        float M2 = __shfl_xor_sync(0xffffffffu, M, 1);
        float S2 = __shfl_xor_sync(0xffffffffu, S, 1);
        float Mn = fmaxf(M, M2);
        S = S * expf(M - Mn) + S2 * expf(M2 - Mn);
        if (q2 == 0) {
            r1[b] = g_sy[b] - Mn - logf(S);     // logp[b, y[b]]
            r2[b] = sqrtf(g_feat_n2[b]);
        }
    }
    __syncthreads();
    for (int stp = 128; stp > 0; stp >>= 1) {
        if (tid < stp) { r1[tid] += r1[tid + stp]; r2[tid] += r2[tid + stp]; }
        __syncthreads();
    }
    if (tid == 0) {
        out[(size_t)B_ * P_]     = -r1[0] / (float)B_;  // loss
        out[(size_t)B_ * P_ + 1] =  r2[0] / (float)B_;  // reg_e
        g_done = 0;                              // reset for graph replay
    }
}

// ---------------- launch ----------------------------------------------------
extern "C" void kernel_launch(void* const* d_in, const int* in_sizes, int n_in,
                              void* d_out, int out_size)
{
    const float* x       = (const float*)d_in[0];
    const int*   y       = (const int*)  d_in[1];
    const float* Wb      = (const float*)d_in[2];
    const float* bb      = (const float*)d_in[3];
    const float* Wm      = (const float*)d_in[4];
    const float* bm      = (const float*)d_in[5];
    const float* proxies = (const float*)d_in[6];
    float* out = (float*)d_out;

    const int SMEM1 = (4 * 64 * RS_W + 4) * 4;                             // 45072 B
    const int SMEM2 = (2 * (128 + 64) * RS_W + 64 + 128 + 1024 + 4) * 4;   // 72464 B
    cudaFuncSetAttribute(gemm1_mma,  cudaFuncAttributeMaxDynamicSharedMemorySize, SMEM1);
    cudaFuncSetAttribute(gemm23_mma, cudaFuncAttributeMaxDynamicSharedMemorySize, SMEM2);

    // 1) feat: split-K GEMM + fused last-slice combine (128 CTAs)
    gemm1_mma<<<dim3(D_ / 64, B_ / 64, SPLITK), 512, SMEM1>>>(x, Wb, bb);
    // 2) fused out-head + proxy softmax partials + last-CTA finalize
    gemm23_mma<<<dim3(64, B_ / 128), 512, SMEM2>>>(Wm, bm, proxies, y, out);
}

// round 14
// speedup vs baseline: 1.2797x; 1.1673x over previous
#include <cuda_runtime.h>
#include <cuda_bf16.h>
#include <math.h>
#include <stdint.h>

#define B_   256
#define IN_  1024
#define D_   512
#define P_   2048
#define SPLITK 4
#define NT_P  (P_ / 64)     // 32 proxy n-tiles per row

// ---------------- scratch (device globals; no allocations allowed) ---------
__device__ float g_feat_part[SPLITK * B_ * D_];   // split-K partials for GEMM1
__device__ float g_featT[B_ * D_];                // tf32-rounded feat
__device__ float g_feat_n2[B_];                   // per-row ||feat||^2 (rounded feat)
__device__ float g_pmax[B_ * NT_P];               // per (row, n-tile) partial max
__device__ float g_psum[B_ * NT_P];               // per (row, n-tile) partial sumexp
__device__ float g_sy[B_];                        // s[b, y[b]]
__device__ int   g_grp[32];                       // per-(m0,n0) split-K counters
__device__ int   g_done;                          // proxy-CTA completion counter

// ==================== tf32 mma.sync helpers ================================
__device__ __forceinline__ void mma_tf32(float c[4], const uint32_t a[4], const uint32_t b[2]) {
    asm volatile("mma.sync.aligned.m16n8k8.row.col.f32.tf32.tf32.f32 "
        "{%0,%1,%2,%3}, {%4,%5,%6,%7}, {%8,%9}, {%0,%1,%2,%3};"
        : "+f"(c[0]), "+f"(c[1]), "+f"(c[2]), "+f"(c[3])
        : "r"(a[0]), "r"(a[1]), "r"(a[2]), "r"(a[3]), "r"(b[0]), "r"(b[1]));
}

__device__ __forceinline__ float to_tf32(float x) {
    uint32_t r;
    asm("cvt.rna.tf32.f32 %0, %1;" : "=r"(r) : "f"(x));
    return __uint_as_float(r);
}
__device__ __forceinline__ uint32_t fu(float x) { return __float_as_uint(x); }

// SMEM: plain row-major, row stride 36 words (144B). Fragment reads are
// LDS.32: bank = (36*g + t) mod 32 = (4g + t) mod 32 -> all 32 lanes
// distinct -> conflict-free. Loader STS.128 phases (8 lanes, same row-group)
// cover banks 4(r+u)..+3, all distinct -> conflict-free.
#define RS_W 36

// One Kc=32 chunk of warp mma from row-major smem (LDS.32 fragments).
template<int WM16, int WN8>
__device__ __forceinline__ void chunk_mma(const float* __restrict__ As,
        const float* __restrict__ Bs, int wm, int wn, int g, int t,
        float acc[WM16][WN8][4])
{
#pragma unroll
    for (int j = 0; j < 4; j++) {
        uint32_t af[WM16][4];
#pragma unroll
        for (int i = 0; i < WM16; i++) {
            const float* base = As + (wm + i * 16 + g) * RS_W + j * 8 + t;
            af[i][0] = fu(base[0]);
            af[i][1] = fu(base[8 * RS_W]);
            af[i][2] = fu(base[4]);
            af[i][3] = fu(base[8 * RS_W + 4]);
        }
        uint32_t bf[WN8][2];
#pragma unroll
        for (int nn = 0; nn < WN8; nn++) {
            const float* base = Bs + (wn + nn * 8 + g) * RS_W + j * 8 + t;
            bf[nn][0] = fu(base[0]);
            bf[nn][1] = fu(base[4]);
        }
#pragma unroll
        for (int i = 0; i < WM16; i++)
#pragma unroll
            for (int nn = 0; nn < WN8; nn++)
                mma_tf32(acc[i][nn], af[i], bf[nn]);
    }
}

// ---------------- GEMM1: x @ Wb^T split-K + fused last-slice combine -------
// Loader: 8 warps x 16 rows; LDG instr i covers rows 4i..4i+3 contiguously
// (4 lines/instr). All 16 warps do mma (warp tile 16x16).
__global__ __launch_bounds__(512, 1)
void gemm1_mma(const float* __restrict__ x, const float* __restrict__ Wb,
               const float* __restrict__ bb)
{
    extern __shared__ __align__(16) float smem[];
    constexpr int TW = 64 * RS_W;               // 2304 words per segment
    constexpr int STG = 2 * TW;                 // A seg + B seg
    int* flag = (int*)(smem + 2 * STG);

    const int tid = threadIdx.x, wid = tid >> 5, lane = tid & 31;
    const int g = lane >> 2, t = lane & 3;
    const int n0 = blockIdx.x * 64, m0 = blockIdx.y * 64;
    const int z  = blockIdx.z;
    const int kb4 = (z * (IN_ / SPLITK)) >> 2;  // K-slice offset in float4
    const int wm = (wid & 3) * 16, wn = (wid >> 2) * 16;

    // loader mapping
    const bool act = tid < 256;
    const int sub = lane >> 3, u = lane & 7;
    const bool ldA = wid < 4;
    const int rbase = (ldA ? wid * 16 : (wid - 4) * 16) + sub;    // + 4i later
    const float4* rp4 = (const float4*)(ldA ? (x + (size_t)(m0 + rbase) * IN_)
                                            : (Wb + (size_t)(n0 + rbase) * IN_));
    const int wbase = (ldA ? 0 : TW) + rbase * RS_W + u * 4;

    float acc[1][2][4] = {};
    float4 v[4];

    auto ld = [&](int c) {
        if (act) {
#pragma unroll
            for (int i = 0; i < 4; i++)
                v[i] = rp4[(size_t)i * (IN_ / 4) * 4 + kb4 + c * 8 + u];
        }
    };
    auto st = [&](int c) {
        if (act) {
            float* base = smem + (c & 1) * STG + wbase;
#pragma unroll
            for (int i = 0; i < 4; i++)
                *(float4*)(base + i * 4 * RS_W) =
                    make_float4(to_tf32(v[i].x), to_tf32(v[i].y),
                                to_tf32(v[i].z), to_tf32(v[i].w));
        }
    };

    ld(0); st(0); __syncthreads();
    constexpr int NCH = (IN_ / SPLITK) / 32;    // 8
    for (int c = 0; c < NCH; c++) {
        if (c + 1 < NCH) ld(c + 1);
        const float* stg = smem + (c & 1) * STG;
        chunk_mma<1, 2>(stg, stg + TW, wm, wn, g, t, acc);
        if (c + 1 < NCH) { st(c + 1); __syncthreads(); }
    }

    // write this slice's partials
    const int m = m0 + wm + g;
    {
        float* dst = g_feat_part + (size_t)z * B_ * D_;
#pragma unroll
        for (int nn = 0; nn < 2; nn++) {
            int n = n0 + wn + nn * 8 + 2 * t;
            *(float2*)(dst + (size_t)m * D_ + n)       = make_float2(acc[0][nn][0], acc[0][nn][1]);
            *(float2*)(dst + (size_t)(m + 8) * D_ + n) = make_float2(acc[0][nn][2], acc[0][nn][3]);
        }
    }

    // ---- last slice of this (m0,n0) group combines + bias + round ----------
    const int gid = blockIdx.y * 8 + blockIdx.x;
    __threadfence();
    __syncthreads();
    if (tid == 0) *flag = (atomicAdd(&g_grp[gid], 1) == SPLITK - 1) ? 1 : 0;
    __syncthreads();
    if (*flag == 0) return;
    __threadfence();                            // acquire other slices' writes

    float2 r0[2], r8[2];
#pragma unroll
    for (int nn = 0; nn < 2; nn++) {
        int n = n0 + wn + nn * 8 + 2 * t;
        float bn0 = bb[n], bn1 = bb[n + 1];
        r0[nn] = make_float2(acc[0][nn][0] + bn0, acc[0][nn][1] + bn1);
        r8[nn] = make_float2(acc[0][nn][2] + bn0, acc[0][nn][3] + bn1);
    }
    for (int zz = 0; zz < SPLITK; zz++) {
        if (zz == z) continue;
        const float* base = g_feat_part + (size_t)zz * B_ * D_;
#pragma unroll
        for (int nn = 0; nn < 2; nn++) {
            int n = n0 + wn + nn * 8 + 2 * t;
            float2 p0 = *(const float2*)(base + (size_t)m * D_ + n);
            float2 p8 = *(const float2*)(base + (size_t)(m + 8) * D_ + n);
            r0[nn].x += p0.x; r0[nn].y += p0.y;
            r8[nn].x += p8.x; r8[nn].y += p8.y;
        }
    }
#pragma unroll
    for (int nn = 0; nn < 2; nn++) {
        int n = n0 + wn + nn * 8 + 2 * t;
        *(float2*)(g_featT + (size_t)m * D_ + n) =
            make_float2(to_tf32(r0[nn].x), to_tf32(r0[nn].y));
        *(float2*)(g_featT + (size_t)(m + 8) * D_ + n) =
            make_float2(to_tf32(r8[nn].x), to_tf32(r8[nn].y));
    }
    __syncthreads();
    if (tid == 0) atomicExch(&g_grp[gid], 0);   // reset for graph replay
}

// ---------------- fused GEMM2 (out) + GEMM3 + last-CTA finalize ------------
// Tile 128(m) x 64(n), K=512. grid (64, 2), 512 thr. Loader: 12 warps x 16
// rows, contiguous LDG (4 lines/instr); mma warp tile 32x16.
__global__ __launch_bounds__(512, 1)
void gemm23_mma(const float* __restrict__ Wm, const float* __restrict__ bm,
                const float* __restrict__ proxies, const int* __restrict__ y,
                float* __restrict__ out)
{
    extern __shared__ __align__(16) float smem[];
    constexpr int TAW = 128 * RS_W;             // 4608 words
    constexpr int TBW = 64 * RS_W;              // 2304
    constexpr int STG = TAW + TBW;
    float* pn2s = smem + 2 * STG;               // [64]
    float* fn2s = pn2s + 64;                    // [128]
    float* pmx  = fn2s + 128;                   // [128][4]  (reused by finalize)
    float* psm  = pmx + 512;                    // [128][4]
    int*   flag = (int*)(psm + 512);

    const int tid = threadIdx.x, wid = tid >> 5, lane = tid & 31;
    const int g = lane >> 2, t = lane & 3;
    const int nt = blockIdx.x;                  // 0..63
    const bool isp = (nt >= 32);
    const int n0 = (nt & 31) * 64;
    const int m0 = blockIdx.y * 128;
    const float* Bmat = isp ? proxies : Wm;
    const int wm = (wid & 3) * 32, wn = (wid >> 2) * 16, wc = wid >> 2;

    // loader mapping: 12 warps (A: 0-7, B: 8-11), 16 rows each
    const bool act = tid < 384;
    const int sub = lane >> 3, u = lane & 7;
    const bool ldA = wid < 8;
    const int rbase = (ldA ? wid * 16 : (wid - 8) * 16) + sub;    // + 4i later
    const float4* rp4 = (const float4*)(ldA ? (g_featT + (size_t)(m0 + rbase) * D_)
                                            : (Bmat + (size_t)(n0 + rbase) * D_));
    const int wbase = (ldA ? 0 : TAW) + rbase * RS_W + u * 4;

    float acc[2][2][4] = {};
    float4 v[4];
    float sq[4] = {0.f, 0.f, 0.f, 0.f};         // per i-row sumsq

    auto ld = [&](int c) {
        if (act) {
#pragma unroll
            for (int i = 0; i < 4; i++)
                v[i] = rp4[(size_t)i * (D_ / 4) * 4 + c * 8 + u];
        }
    };
    auto st = [&](int c) {
        if (act) {
            float* base = smem + (c & 1) * STG + wbase;
#pragma unroll
            for (int i = 0; i < 4; i++) {
                float4 a = v[i];
                sq[i] += a.x * a.x + a.y * a.y + a.z * a.z + a.w * a.w;
                if (ldA)     // featT already tf32-rounded
                    *(float4*)(base + i * 4 * RS_W) = a;
                else
                    *(float4*)(base + i * 4 * RS_W) =
                        make_float4(to_tf32(a.x), to_tf32(a.y),
                                    to_tf32(a.z), to_tf32(a.w));
            }
        }
    };

    ld(0); st(0); __syncthreads();
    constexpr int NCH = D_ / 32;                // 16
    for (int c = 0; c < NCH; c++) {
        if (c + 1 < NCH) ld(c + 1);
        const float* stg = smem + (c & 1) * STG;
        chunk_mma<2, 2>(stg, stg + TAW, wm, wn, g, t, acc);
        if (c + 1 < NCH) { st(c + 1); __syncthreads(); }
    }

    // per-row sumsq: reduce over the 8 u-lanes (same sub group)
    if (act) {
#pragma unroll
        for (int i = 0; i < 4; i++) {
            float s = sq[i];
            s += __shfl_xor_sync(0xffffffffu, s, 1);
            s += __shfl_xor_sync(0xffffffffu, s, 2);
            s += __shfl_xor_sync(0xffffffffu, s, 4);
            if (u == 0) {
                int row = rbase + 4 * i;
                if (ldA) fn2s[row] = s;
                else     pn2s[row] = s;
            }
        }
    }
    __syncthreads();

    if (!isp) {
#pragma unroll
        for (int i = 0; i < 2; i++) {
            int m = m0 + wm + i * 16 + g;
#pragma unroll
            for (int nn = 0; nn < 2; nn++) {
                int n = n0 + wn + nn * 8 + 2 * t;
                float bn0 = bm[n], bn1 = bm[n + 1];
                *(float2*)(out + (size_t)m * P_ + n) =
                    make_float2(acc[i][nn][0] + bn0, acc[i][nn][1] + bn1);
                *(float2*)(out + (size_t)(m + 8) * P_ + n) =
                    make_float2(acc[i][nn][2] + bn0, acc[i][nn][3] + bn1);
            }
        }
        return;
    }

    // export fn2 for reg_e (2 CTAs cover all 256 rows)
    if (nt == 32 && tid < 128) g_feat_n2[m0 + tid] = fn2s[tid];

    // proxy: s = 2*dot - fn2 - pn2 in regs -> per-(row, warp) (max, sumexp)
#pragma unroll
    for (int i = 0; i < 2; i++) {
        const int rA = wm + i * 16 + g;
        const int rB = rA + 8;
        const float fa = fn2s[rA], fb = fn2s[rB];
        const int ya = y[m0 + rA], yb = y[m0 + rB];
        float sA[4], sB[4];
#pragma unroll
        for (int nn = 0; nn < 2; nn++) {
            int nl = wn + nn * 8 + 2 * t;
            float p0 = pn2s[nl], p1 = pn2s[nl + 1];
            sA[nn * 2 + 0] = 2.f * acc[i][nn][0] - fa - p0;
            sA[nn * 2 + 1] = 2.f * acc[i][nn][1] - fa - p1;
            sB[nn * 2 + 0] = 2.f * acc[i][nn][2] - fb - p0;
            sB[nn * 2 + 1] = 2.f * acc[i][nn][3] - fb - p1;
            int n = n0 + nl;
            if (n     == ya) g_sy[m0 + rA] = sA[nn * 2 + 0];
            if (n + 1 == ya) g_sy[m0 + rA] = sA[nn * 2 + 1];
            if (n     == yb) g_sy[m0 + rB] = sB[nn * 2 + 0];
            if (n + 1 == yb) g_sy[m0 + rB] = sB[nn * 2 + 1];
        }
        float mA = fmaxf(fmaxf(sA[0], sA[1]), fmaxf(sA[2], sA[3]));
        float mB = fmaxf(fmaxf(sB[0], sB[1]), fmaxf(sB[2], sB[3]));
        float eA = expf(sA[0] - mA) + expf(sA[1] - mA)
                 + expf(sA[2] - mA) + expf(sA[3] - mA);
        float eB = expf(sB[0] - mB) + expf(sB[1] - mB)
                 + expf(sB[2] - mB) + expf(sB[3] - mB);
#pragma unroll
        for (int o = 1; o <= 2; o <<= 1) {
            float mA2 = __shfl_xor_sync(0xffffffffu, mA, o);
            float eA2 = __shfl_xor_sync(0xffffffffu, eA, o);
            float mB2 = __shfl_xor_sync(0xffffffffu, mB, o);
            float eB2 = __shfl_xor_sync(0xffffffffu, eB, o);
            float M = fmaxf(mA, mA2);
            eA = eA * expf(mA - M) + eA2 * expf(mA2 - M); mA = M;
            M = fmaxf(mB, mB2);
            eB = eB * expf(mB - M) + eB2 * expf(mB2 - M); mB = M;
        }
        if (t == 0) {
            pmx[rA * 4 + wc] = mA; psm[rA * 4 + wc] = eA;
            pmx[rB * 4 + wc] = mB; psm[rB * 4 + wc] = eB;
        }
    }
    __syncthreads();
    if (tid < 128) {
        float4 m4 = *(const float4*)(pmx + tid * 4);
        float4 s4 = *(const float4*)(psm + tid * 4);
        float M = fmaxf(fmaxf(m4.x, m4.y), fmaxf(m4.z, m4.w));
        float S = s4.x * expf(m4.x - M) + s4.y * expf(m4.y - M)
                + s4.z * expf(m4.z - M) + s4.w * expf(m4.w - M);
        int idx = (m0 + tid) * NT_P + (nt - 32);
        g_pmax[idx] = M;
        g_psum[idx] = S;
    }

    // ---- last-done proxy CTA finalizes loss + reg_e ------------------------
    __threadfence();
    __syncthreads();
    if (tid == 0) *flag = (atomicAdd(&g_done, 1) == 63) ? 1 : 0;
    __syncthreads();
    if (*flag == 0) return;
    __threadfence();

    float* r1 = pmx;                            // reuse smem [256]
    float* r2 = pmx + 256;
    {
        const int b = tid >> 1, q2 = tid & 1;
        const float4* pm = (const float4*)(g_pmax + b * NT_P + q2 * 16);
        const float4* ps = (const float4*)(g_psum + b * NT_P + q2 * 16);
        float4 m0v = pm[0], m1v = pm[1], m2v = pm[2], m3v = pm[3];
        float4 s0v = ps[0], s1v = ps[1], s2v = ps[2], s3v = ps[3];
        float M = fmaxf(fmaxf(fmaxf(m0v.x, m0v.y), fmaxf(m0v.z, m0v.w)),
                        fmaxf(fmaxf(m1v.x, m1v.y), fmaxf(m1v.z, m1v.w)));
        M = fmaxf(M, fmaxf(fmaxf(fmaxf(m2v.x, m2v.y), fmaxf(m2v.z, m2v.w)),
                           fmaxf(fmaxf(m3v.x, m3v.y), fmaxf(m3v.z, m3v.w))));
        float S = s0v.x * expf(m0v.x - M) + s0v.y * expf(m0v.y - M)
                + s0v.z * expf(m0v.z - M) + s0v.w * expf(m0v.w - M)
                + s1v.x * expf(m1v.x - M) + s1v.y * expf(m1v.y - M)
                + s1v.z * expf(m1v.z - M) + s1v.w * expf(m1v.w - M)
                + s2v.x * expf(m2v.x - M) + s2v.y * expf(m2v.y - M)
                + s2v.z * expf(m2v.z - M) + s2v.w * expf(m2v.w - M)
                + s3v.x * expf(m3v.x - M) + s3v.y * expf(m3v.y - M)
                + s3v.z * expf(m3v.z - M) + s3v.w * expf(m3v.w - M);
        float M2 = __shfl_xor_sync(0xffffffffu, M, 1);
        float S2 = __shfl_xor_sync(0xffffffffu, S, 1);
        float Mn = fmaxf(M, M2);
        S = S * expf(M - Mn) + S2 * expf(M2 - Mn);
        if (q2 == 0) {
            r1[b] = g_sy[b] - Mn - logf(S);     // logp[b, y[b]]
            r2[b] = sqrtf(g_feat_n2[b]);
        }
    }
    __syncthreads();
    for (int stp = 128; stp > 0; stp >>= 1) {
        if (tid < stp) { r1[tid] += r1[tid + stp]; r2[tid] += r2[tid + stp]; }
        __syncthreads();
    }
    if (tid == 0) {
        out[(size_t)B_ * P_]     = -r1[0] / (float)B_;  // loss
        out[(size_t)B_ * P_ + 1] =  r2[0] / (float)B_;  // reg_e
        g_done = 0;                              // reset for graph replay
    }
}

// ---------------- launch ----------------------------------------------------
extern "C" void kernel_launch(void* const* d_in, const int* in_sizes, int n_in,
                              void* d_out, int out_size)
{
    const float* x       = (const float*)d_in[0];
    const int*   y       = (const int*)  d_in[1];
    const float* Wb      = (const float*)d_in[2];
    const float* bb      = (const float*)d_in[3];
    const float* Wm      = (const float*)d_in[4];
    const float* bm      = (const float*)d_in[5];
    const float* proxies = (const float*)d_in[6];
    float* out = (float*)d_out;

    const int SMEM1 = (4 * 64 * RS_W + 4) * 4;                             // ~36.9 KB
    const int SMEM2 = (2 * (128 + 64) * RS_W + 64 + 128 + 1024 + 4) * 4;   // ~60.1 KB
    cudaFuncSetAttribute(gemm1_mma,  cudaFuncAttributeMaxDynamicSharedMemorySize, SMEM1);
    cudaFuncSetAttribute(gemm23_mma, cudaFuncAttributeMaxDynamicSharedMemorySize, SMEM2);

    // 1) feat: split-K GEMM + fused last-slice combine (128 CTAs)
    gemm1_mma<<<dim3(D_ / 64, B_ / 64, SPLITK), 512, SMEM1>>>(x, Wb, bb);
    // 2) fused out-head + proxy softmax partials + last-CTA finalize
    gemm23_mma<<<dim3(64, B_ / 128), 512, SMEM2>>>(Wm, bm, proxies, y, out);
}